// round 3
// baseline (speedup 1.0000x reference)
#include <cuda_runtime.h>
#include <cstddef>

#define NAPP 100000
#define NATTR 50000
#define NEDGE 500000
#define D 128

// ---------------- scratch (device globals; no allocation allowed) ----------------
__device__ __align__(256) float g_s0[NATTR * D];
__device__ __align__(256) float g_s1[NAPP * D];
__device__ __align__(256) float g_s2[NAPP * D];
__device__ __align__(256) float g_s1b[NAPP * D];
__device__ __align__(256) float g_s2b[NAPP * D];
__device__ __align__(256) float g_deg0[NATTR];
__device__ __align__(256) float g_deg1[NAPP];
__device__ __align__(256) float g_deg2[NAPP];
__device__ __align__(256) float g_inv0[NATTR];
__device__ __align__(256) float g_inv1[NAPP];
__device__ __align__(256) float g_inv2[NAPP];
__device__ __align__(256) float g_hattr[NATTR * D];
__device__ __align__(256) float g_happ[NAPP * D];
__device__ __align__(256) float g_WappSelf[D * D];
__device__ __align__(256) float g_bapp[D];
__device__ __align__(256) float g_Wsc[D * 2];
__device__ __align__(256) float g_Wn1c[D * 2];
__device__ __align__(256) float g_Wn2c[D * 2];
__device__ __align__(256) float g_bc2[2];

// ---------------- zero scratch accumulators ----------------
__global__ void zero_kernel() {
    size_t stride = (size_t)gridDim.x * blockDim.x;
    size_t gt = (size_t)blockIdx.x * blockDim.x + threadIdx.x;
    float4 z = make_float4(0.f, 0.f, 0.f, 0.f);
    for (size_t i = gt; i < (size_t)NATTR * D / 4; i += stride) ((float4*)g_s0)[i] = z;
    for (size_t i = gt; i < (size_t)NAPP * D / 4; i += stride) {
        ((float4*)g_s1)[i] = z;
        ((float4*)g_s2)[i] = z;
        ((float4*)g_s1b)[i] = z;
        ((float4*)g_s2b)[i] = z;
    }
    for (size_t i = gt; i < NAPP; i += stride) {
        g_deg1[i] = 0.f; g_deg2[i] = 0.f;
        if (i < NATTR) g_deg0[i] = 0.f;
    }
}

// ---------------- fold weights: Wself1[1]+Wself1[2], b1[1]+b1[2], and layer2@Wc ----------------
__global__ void prep_kernel(const float* __restrict__ Wself1, const float* __restrict__ b1,
                            const float* __restrict__ Wself2, const float* __restrict__ Wneigh2,
                            const float* __restrict__ b2, const float* __restrict__ Wc,
                            const float* __restrict__ bc) {
    int t = threadIdx.x;
    for (int idx = t; idx < D * D; idx += 256)
        g_WappSelf[idx] = Wself1[D * D + idx] + Wself1[2 * D * D + idx];
    if (t < D) g_bapp[t] = b1[D + t] + b1[2 * D + t];
    {
        int k = t >> 1, o = t & 1;
        float sWs = 0.f, sW1 = 0.f, sW2 = 0.f;
        for (int j = 0; j < D; j++) {
            float wc = Wc[j * 2 + o];
            sWs += (Wself2[D * D + k * D + j] + Wself2[2 * D * D + k * D + j]) * wc;
            sW1 += Wneigh2[D * D + k * D + j] * wc;
            sW2 += Wneigh2[2 * D * D + k * D + j] * wc;
        }
        g_Wsc[k * 2 + o] = sWs;
        g_Wn1c[k * 2 + o] = sW1;
        g_Wn2c[k * 2 + o] = sW2;
    }
    if (t < 2) {
        float s = bc[t];
        for (int j = 0; j < D; j++) s += (b2[D + j] + b2[2 * D + j]) * Wc[j * 2 + t];
        g_bc2[t] = s;
    }
}

// ---------------- edge scatter: s[dst] += ew * hsrc[src]; deg[dst] += 1 ----------------
__global__ __launch_bounds__(256) void scatter_kernel(
    const float* __restrict__ hsrc, const int* __restrict__ src,
    const int* __restrict__ dst, const float* __restrict__ ew,
    float* __restrict__ s, float* __restrict__ deg) {
    int gt = blockIdx.x * 256 + threadIdx.x;
    int e = gt >> 5;
    if (e >= NEDGE) return;
    int lane = gt & 31;
    int sR = __ldg(src + e);
    int dR = __ldg(dst + e);
    float w = __ldg(ew + e);
    float4 v = __ldg((const float4*)(hsrc + (size_t)sR * D) + lane);
    v.x *= w; v.y *= w; v.z *= w; v.w *= w;
    float* p = s + (size_t)dR * D + lane * 4;
    asm volatile("red.global.add.v4.f32 [%0], {%1,%2,%3,%4};"
                 :: "l"(p), "f"(v.x), "f"(v.y), "f"(v.z), "f"(v.w) : "memory");
    if (deg != nullptr && lane == 0) atomicAdd(deg + dR, 1.0f);
}

// ---------------- inv degree ----------------
__global__ void invdeg_kernel() {
    int i = blockIdx.x * 256 + threadIdx.x;
    if (i < NAPP) {
        g_inv1[i] = 1.0f / fmaxf(g_deg1[i], 1.0f);
        g_inv2[i] = 1.0f / fmaxf(g_deg2[i], 1.0f);
        if (i < NATTR) g_inv0[i] = 1.0f / fmaxf(g_deg0[i], 1.0f);
    }
}

// ---------------- C = relu( sum_j (A_j * rowscale_j) @ W_j + bias ), K_j = 128 each ----------------
__global__ __launch_bounds__(256, 2) void gemm_relu_kernel(
    const float* __restrict__ A0, const float* __restrict__ I0,
    const float* __restrict__ A1, const float* __restrict__ I1,
    const float* __restrict__ A2, const float* __restrict__ I2,
    const float* __restrict__ W0, const float* __restrict__ W1, const float* __restrict__ W2,
    const float* __restrict__ bias, float* __restrict__ C, int M, int nin) {
    __shared__ float As[32][68];   // [k][row], row stride 68 floats -> 16B-aligned rows, conflict-free
    __shared__ float Bs[32][128];  // [k][col]
    const int t = threadIdx.x;
    const int row0 = blockIdx.x * 64;
    const int trow = t >> 4;  // 0..15 -> 4 rows each
    const int tcol = t & 15;  // 0..15 -> 8 cols each
    float acc[4][8];
#pragma unroll
    for (int i = 0; i < 4; i++)
#pragma unroll
        for (int j = 0; j < 8; j++) acc[i][j] = 0.f;

    const float* Aj[3] = {A0, A1, A2};
    const float* Ij[3] = {I0, I1, I2};
    const float* Wj[3] = {W0, W1, W2};

    for (int jj = 0; jj < nin; jj++) {
        const float* A = Aj[jj];
        const float* I = Ij[jj];
        const float* W = Wj[jj];
        for (int kc = 0; kc < 4; kc++) {
            const int k0 = kc * 32;
            __syncthreads();
            // A tile: 64 rows x 32 k  (512 float4 loads, transposed store)
#pragma unroll
            for (int i = 0; i < 2; i++) {
                int f = t * 2 + i;
                int r = f >> 3;
                int kq = f & 7;
                int grow = row0 + r;
                float4 v = make_float4(0.f, 0.f, 0.f, 0.f);
                if (grow < M) {
                    v = *(const float4*)(A + (size_t)grow * 128 + k0 + kq * 4);
                    if (I) { float sc = I[grow]; v.x *= sc; v.y *= sc; v.z *= sc; v.w *= sc; }
                }
                As[kq * 4 + 0][r] = v.x;
                As[kq * 4 + 1][r] = v.y;
                As[kq * 4 + 2][r] = v.z;
                As[kq * 4 + 3][r] = v.w;
            }
            // W tile: 32 k x 128 cols
#pragma unroll
            for (int i = 0; i < 4; i++) {
                int f = i * 256 + t;
                int kk = f >> 5;
                int cq = f & 31;
                *(float4*)&Bs[kk][cq * 4] =
                    *(const float4*)(W + (size_t)(k0 + kk) * 128 + cq * 4);
            }
            __syncthreads();
#pragma unroll
            for (int kk = 0; kk < 32; kk++) {
                float4 a = *(const float4*)&As[kk][trow * 4];
                float4 b0 = *(const float4*)&Bs[kk][tcol * 8];
                float4 b1v = *(const float4*)&Bs[kk][tcol * 8 + 4];
                float av[4] = {a.x, a.y, a.z, a.w};
                float bv[8] = {b0.x, b0.y, b0.z, b0.w, b1v.x, b1v.y, b1v.z, b1v.w};
#pragma unroll
                for (int i = 0; i < 4; i++)
#pragma unroll
                    for (int j = 0; j < 8; j++)
                        acc[i][j] = fmaf(av[i], bv[j], acc[i][j]);
            }
        }
    }
    int col = tcol * 8;
    float4 bA = *(const float4*)(bias + col);
    float4 bB = *(const float4*)(bias + col + 4);
    float bb[8] = {bA.x, bA.y, bA.z, bA.w, bB.x, bB.y, bB.z, bB.w};
#pragma unroll
    for (int i = 0; i < 4; i++) {
        int grow = row0 + trow * 4 + i;
        if (grow < M) {
            float o[8];
#pragma unroll
            for (int j = 0; j < 8; j++) o[j] = fmaxf(acc[i][j] + bb[j], 0.f);
            *(float4*)(C + (size_t)grow * 128 + col) = make_float4(o[0], o[1], o[2], o[3]);
            *(float4*)(C + (size_t)grow * 128 + col + 4) = make_float4(o[4], o[5], o[6], o[7]);
        }
    }
}

// ---------------- fused layer2 + classifier: out[i] = happ@Wsc + n1'@Wn1c + n2'@Wn2c + bc2 ----------------
__global__ __launch_bounds__(256) void final_kernel(float* __restrict__ out) {
    int gt = blockIdx.x * 256 + threadIdx.x;
    int i = gt >> 5;
    if (i >= NAPP) return;
    int lane = gt & 31;
    float4 h = ((const float4*)(g_happ + (size_t)i * D))[lane];
    float4 n1 = ((const float4*)(g_s1b + (size_t)i * D))[lane];
    float4 n2 = ((const float4*)(g_s2b + (size_t)i * D))[lane];
    float i1 = g_inv1[i], i2 = g_inv2[i];
    n1.x *= i1; n1.y *= i1; n1.z *= i1; n1.w *= i1;
    n2.x *= i2; n2.y *= i2; n2.z *= i2; n2.w *= i2;
    float hv[4] = {h.x, h.y, h.z, h.w};
    float n1v[4] = {n1.x, n1.y, n1.z, n1.w};
    float n2v[4] = {n2.x, n2.y, n2.z, n2.w};
    int k = lane * 4;
    float a0 = 0.f, a1 = 0.f;
#pragma unroll
    for (int c = 0; c < 4; c++) {
        a0 += hv[c] * g_Wsc[(k + c) * 2 + 0] + n1v[c] * g_Wn1c[(k + c) * 2 + 0] +
              n2v[c] * g_Wn2c[(k + c) * 2 + 0];
        a1 += hv[c] * g_Wsc[(k + c) * 2 + 1] + n1v[c] * g_Wn1c[(k + c) * 2 + 1] +
              n2v[c] * g_Wn2c[(k + c) * 2 + 1];
    }
#pragma unroll
    for (int off = 16; off; off >>= 1) {
        a0 += __shfl_down_sync(0xffffffffu, a0, off);
        a1 += __shfl_down_sync(0xffffffffu, a1, off);
    }
    if (lane == 0) {
        out[2 * i + 0] = a0 + g_bc2[0];
        out[2 * i + 1] = a1 + g_bc2[1];
    }
}

extern "C" void kernel_launch(void* const* d_in, const int* in_sizes, int n_in,
                              void* d_out, int out_size) {
    const float* x_app = (const float*)d_in[0];
    const float* x_attr = (const float*)d_in[1];
    const float* ew0 = (const float*)d_in[2];
    const float* ew1 = (const float*)d_in[3];
    const float* ew2 = (const float*)d_in[4];
    const float* Wself1 = (const float*)d_in[5];
    const float* Wneigh1 = (const float*)d_in[6];
    const float* b1 = (const float*)d_in[7];
    const float* Wself2 = (const float*)d_in[8];
    const float* Wneigh2 = (const float*)d_in[9];
    const float* b2 = (const float*)d_in[10];
    const float* Wc = (const float*)d_in[11];
    const float* bc = (const float*)d_in[12];
    const int* src0 = (const int*)d_in[13];
    const int* dst0 = (const int*)d_in[14];
    const int* src1 = (const int*)d_in[15];
    const int* dst1 = (const int*)d_in[16];
    const int* src2 = (const int*)d_in[17];
    const int* dst2 = (const int*)d_in[18];
    float* out = (float*)d_out;

    float *s0, *s1, *s2, *s1b, *s2b, *deg0, *deg1, *deg2;
    float *inv0, *inv1, *inv2, *hattr, *happ, *WappSelf, *bapp;
    cudaGetSymbolAddress((void**)&s0, g_s0);
    cudaGetSymbolAddress((void**)&s1, g_s1);
    cudaGetSymbolAddress((void**)&s2, g_s2);
    cudaGetSymbolAddress((void**)&s1b, g_s1b);
    cudaGetSymbolAddress((void**)&s2b, g_s2b);
    cudaGetSymbolAddress((void**)&deg0, g_deg0);
    cudaGetSymbolAddress((void**)&deg1, g_deg1);
    cudaGetSymbolAddress((void**)&deg2, g_deg2);
    cudaGetSymbolAddress((void**)&inv0, g_inv0);
    cudaGetSymbolAddress((void**)&inv1, g_inv1);
    cudaGetSymbolAddress((void**)&inv2, g_inv2);
    cudaGetSymbolAddress((void**)&hattr, g_hattr);
    cudaGetSymbolAddress((void**)&happ, g_happ);
    cudaGetSymbolAddress((void**)&WappSelf, g_WappSelf);
    cudaGetSymbolAddress((void**)&bapp, g_bapp);

    zero_kernel<<<2048, 256>>>();
    prep_kernel<<<1, 256>>>(Wself1, b1, Wself2, Wneigh2, b2, Wc, bc);

    const int SCATTER_BLOCKS = (NEDGE * 32) / 256;  // 62500
    // layer 1 aggregations
    scatter_kernel<<<SCATTER_BLOCKS, 256>>>(x_app, src0, dst0, ew0, s0, deg0);
    scatter_kernel<<<SCATTER_BLOCKS, 256>>>(x_attr, src1, dst1, ew1, s1, deg1);
    scatter_kernel<<<SCATTER_BLOCKS, 256>>>(x_app, src2, dst2, ew2, s2, deg2);
    invdeg_kernel<<<(NAPP + 255) / 256, 256>>>();

    // layer 1 dense
    gemm_relu_kernel<<<(NATTR + 63) / 64, 256>>>(
        x_attr, nullptr, s0, inv0, nullptr, nullptr,
        Wself1, Wneigh1, nullptr, b1, hattr, NATTR, 2);
    gemm_relu_kernel<<<(NAPP + 63) / 64, 256>>>(
        x_app, nullptr, s1, inv1, s2, inv2,
        WappSelf, Wneigh1 + D * D, Wneigh1 + 2 * D * D, bapp, happ, NAPP, 3);

    // layer 2 aggregations (attr output of layer 2 is unused -> skipped)
    scatter_kernel<<<SCATTER_BLOCKS, 256>>>(hattr, src1, dst1, ew1, s1b, nullptr);
    scatter_kernel<<<SCATTER_BLOCKS, 256>>>(happ, src2, dst2, ew2, s2b, nullptr);

    // layer 2 + classifier fused (weights pre-folded through Wc)
    final_kernel<<<(NAPP * 32 + 255) / 256, 256>>>(out);
}